// round 1
// baseline (speedup 1.0000x reference)
#include <cuda_runtime.h>

// FlowGradientReg: bilinear warp, x:[B,C,H,W] f32, flow:[B,H,W,2] f32 -> out:[B,C,H,W] f32
// B=32, C=3, H=512, W=512

constexpr int B = 32, C = 3, H = 512, W = 512;
constexpr int HW = H * W;
constexpr int TOTAL = B * HW;

__global__ void __launch_bounds__(256) flow_warp_kernel(
    const float* __restrict__ x,
    const float* __restrict__ flow,
    float* __restrict__ out)
{
    int idx = blockIdx.x * blockDim.x + threadIdx.x;
    if (idx >= TOTAL) return;

    int b  = idx >> 18;          // / HW (HW = 262144 = 2^18)
    int p  = idx & (HW - 1);
    int pi = p >> 9;             // / W
    int pj = p & (W - 1);

    // flow layout [B,H,W,2] contiguous -> float2 per pixel, coalesced
    float2 f = reinterpret_cast<const float2*>(flow)[idx];

    // identity grid (align_corners=True): xs[j] = -1 + 2j/(W-1)
    float gx = fmaf((float)pj, 2.0f / (float)(W - 1), -1.0f) + f.x;
    float gy = fmaf((float)pi, 2.0f / (float)(H - 1), -1.0f) + f.y;

    // normalized -> pixel coords
    float jc = (float)(W - 1) * (gx + 1.0f) * 0.5f;
    float ic = (float)(H - 1) * (gy + 1.0f) * 0.5f;

    // clamp-then-lerp exactly like reference (di/dj measured from clamped i1/j1)
    float i1f = fminf(fmaxf(floorf(ic), 0.0f), (float)(H - 1));
    float i2f = fminf(i1f + 1.0f, (float)(H - 1));
    float j1f = fminf(fmaxf(floorf(jc), 0.0f), (float)(W - 1));
    float j2f = fminf(j1f + 1.0f, (float)(W - 1));

    int i1 = (int)i1f, i2 = (int)i2f, j1 = (int)j1f, j2 = (int)j2f;
    float di = ic - i1f;
    float dj = jc - j1f;

    const float* xb = x   + (size_t)b * C * HW;
    float*       ob = out + (size_t)b * C * HW;

    int r1 = i1 * W;
    int r2 = i2 * W;

    #pragma unroll
    for (int c = 0; c < C; c++) {
        const float* xc = xb + c * HW;
        float q11 = __ldg(xc + r1 + j1);
        float q12 = __ldg(xc + r1 + j2);
        float q21 = __ldg(xc + r2 + j1);
        float q22 = __ldg(xc + r2 + j2);
        float qa = fmaf(di, q21 - q11, q11);   // q11*(1-di) + q21*di
        float qb = fmaf(di, q22 - q12, q12);
        float q  = fmaf(dj, qb - qa, qa);
        ob[c * HW + p] = q;
    }
}

extern "C" void kernel_launch(void* const* d_in, const int* in_sizes, int n_in,
                              void* d_out, int out_size)
{
    const float* x    = (const float*)d_in[0];
    const float* flow = (const float*)d_in[1];
    float* out        = (float*)d_out;

    int threads = 256;
    int blocks  = (TOTAL + threads - 1) / threads;
    flow_warp_kernel<<<blocks, threads>>>(x, flow, out);
}

// round 3
// speedup vs baseline: 1.1267x; 1.1267x over previous
#include <cuda_runtime.h>

// FlowGradientReg: bilinear warp via smem-tiled gather.
// x:[B,C,H,W] f32, flow:[B,H,W,2] f32 -> out:[B,C,H,W] f32
// B=32, C=3, H=512, W=512

constexpr int B = 32, C = 3, H = 512, W = 512;
constexpr int HW = H * W;

constexpr int TSH = 64, TSW = 64;       // tile (output pixels per block)
constexpr int HALO = 16;
constexpr int SH = TSH + 2 * HALO;      // 96 rows covered in smem
constexpr int SWD = TSW + 2 * HALO;     // 96 cols covered
constexpr int SP = SWD + 1;             // 97: pad to kill bank conflicts
constexpr int SMEM_FLOATS = C * SH * SP;            // 3*96*97 = 27936
constexpr int SMEM_BYTES = SMEM_FLOATS * 4;         // 111744

constexpr int THREADS = 512;
constexpr int TILES_X = W / TSW;        // 8
constexpr int TILES_Y = H / TSH;        // 8
constexpr int TILES_PER_IMG = TILES_X * TILES_Y;    // 64
constexpr int NCOL4 = SWD / 4;          // 24 float4 per covered row

__global__ void __launch_bounds__(THREADS) flow_warp_tile_kernel(
    const float* __restrict__ x,
    const float* __restrict__ flow,
    float* __restrict__ out)
{
    extern __shared__ float smem[];   // [C][SH][SP]

    int tid = threadIdx.x;
    int bx  = blockIdx.x;
    int b   = bx >> 6;                 // / TILES_PER_IMG
    int t   = bx & 63;
    int ti0 = (t >> 3) * TSH;
    int tj0 = (t & 7) * TSW;

    const float* xb = x + (size_t)b * C * HW;

    // ---- Phase 1: coalesced load of halo region into smem (float4) ----
    // covered global rows [ti0-16, ti0+80), cols [tj0-16, tj0+80), clipped to image
    #pragma unroll 1
    for (int it = tid; it < C * SH * NCOL4; it += THREADS) {
        int c   = it / (SH * NCOL4);
        int rem = it - c * (SH * NCOL4);
        int r   = rem / NCOL4;
        int q   = rem - r * NCOL4;
        int gr  = ti0 - HALO + r;
        int gc  = tj0 - HALO + 4 * q;
        if ((unsigned)gr < (unsigned)H && (unsigned)gc < (unsigned)W) {
            float4 v = *reinterpret_cast<const float4*>(xb + c * HW + gr * W + gc);
            float* s = smem + (c * SH + r) * SP + (gc - (tj0 - HALO));
            s[0] = v.x; s[1] = v.y; s[2] = v.z; s[3] = v.w;
        }
    }
    __syncthreads();

    // ---- Phase 2: per-pixel bilinear gather from smem ----
    #pragma unroll 1
    for (int k = 0; k < (TSH * TSW) / THREADS; k++) {
        int px  = tid + k * THREADS;
        int row = px >> 6;             // / TSW
        int col = px & 63;
        int gi  = ti0 + row;
        int gj  = tj0 + col;
        int p   = gi * W + gj;

        float2 f = reinterpret_cast<const float2*>(flow)[(size_t)b * HW + p];

        float gx = fmaf((float)gj, 2.0f / (float)(W - 1), -1.0f) + f.x;
        float gy = fmaf((float)gi, 2.0f / (float)(H - 1), -1.0f) + f.y;
        float jc = (float)(W - 1) * (gx + 1.0f) * 0.5f;
        float ic = (float)(H - 1) * (gy + 1.0f) * 0.5f;

        float i1f = fminf(fmaxf(floorf(ic), 0.0f), (float)(H - 1));
        float i2f = fminf(i1f + 1.0f, (float)(H - 1));
        float j1f = fminf(fmaxf(floorf(jc), 0.0f), (float)(W - 1));
        float j2f = fminf(j1f + 1.0f, (float)(W - 1));

        int i1 = (int)i1f, i2 = (int)i2f, j1 = (int)j1f, j2 = (int)j2f;
        float di = ic - i1f;
        float dj = jc - j1f;

        float q11[C], q12[C], q21[C], q22[C];

        bool in_tile = (i1 >= ti0 - HALO) && (i2 <= ti0 + TSH + HALO - 1) &&
                       (j1 >= tj0 - HALO) && (j2 <= tj0 + TSW + HALO - 1);

        if (in_tile) {
            int sr1 = i1 - (ti0 - HALO);
            int sr2 = i2 - (ti0 - HALO);
            int sc1 = j1 - (tj0 - HALO);
            int sc2 = j2 - (tj0 - HALO);
            #pragma unroll
            for (int c = 0; c < C; c++) {
                const float* sb = smem + c * SH * SP;
                q11[c] = sb[sr1 * SP + sc1];
                q12[c] = sb[sr1 * SP + sc2];
                q21[c] = sb[sr2 * SP + sc1];
                q22[c] = sb[sr2 * SP + sc2];
            }
        } else {
            int r1 = i1 * W, r2 = i2 * W;
            #pragma unroll
            for (int c = 0; c < C; c++) {
                const float* xc = xb + c * HW;
                q11[c] = __ldg(xc + r1 + j1);
                q12[c] = __ldg(xc + r1 + j2);
                q21[c] = __ldg(xc + r2 + j1);
                q22[c] = __ldg(xc + r2 + j2);
            }
        }

        float* ob = out + (size_t)b * C * HW + p;
        #pragma unroll
        for (int c = 0; c < C; c++) {
            float qa = fmaf(di, q21[c] - q11[c], q11[c]);
            float qb = fmaf(di, q22[c] - q12[c], q12[c]);
            ob[c * HW] = fmaf(dj, qb - qa, qa);
        }
    }
}

extern "C" void kernel_launch(void* const* d_in, const int* in_sizes, int n_in,
                              void* d_out, int out_size)
{
    const float* x    = (const float*)d_in[0];
    const float* flow = (const float*)d_in[1];
    float* out        = (float*)d_out;

    static bool configured = false;
    if (!configured) {
        cudaFuncSetAttribute(flow_warp_tile_kernel,
                             cudaFuncAttributeMaxDynamicSharedMemorySize, SMEM_BYTES);
        configured = true;
    }

    int blocks = B * TILES_PER_IMG;    // 2048
    flow_warp_tile_kernel<<<blocks, THREADS, SMEM_BYTES>>>(x, flow, out);
}